// round 7
// baseline (speedup 1.0000x reference)
#include <cuda_runtime.h>
#include <cstdint>

// ============================================================================
// RetinaHead: 5 FPN levels, two conv towers (cls 720ch / reg 36ch), postprocess.
// Round 6: 3xTF32 mma implicit-GEMM conv, cp.async double-buffered smem,
//   raw-fp32 tiles split hi/lo at fragment-read, per-k8 chunked accumulation.
// ============================================================================

#define NUM_CLASSES 80
#define NUM_ANCH 9
#define ATOT 49104
#define BATCH 8
#define NMAX (256*32768)

__device__ float g_x[NMAX];                 // transposed input feat [256][N]
__device__ float g_a[NMAX];                 // ping
__device__ float g_b[NMAX];                 // pong
__device__ float g_cls[720 * 32768];        // cls logits [720][N]
__device__ float g_reg[36 * 32768];         // reg deltas [36][N]
__device__ float g_wt[6460416];             // transposed weights [kpos*256+cin][cout]

// Weight transform: src (Cout,256,3,3) -> dst [kpos*256+cin][cout]
__global__ void wt_kernel(const float* __restrict__ src, float* __restrict__ dst, int Cout) {
    int total = 9 * 256 * Cout;
    for (int t = blockIdx.x * blockDim.x + threadIdx.x; t < total; t += gridDim.x * blockDim.x) {
        int cout = t % Cout;
        int rem  = t / Cout;
        int cin  = rem % 256;
        int kpos = rem / 256;
        dst[t] = src[(cout * 256 + cin) * 9 + kpos];
    }
}

// Transpose feat (B,256,H,W) -> [256][B*HW]
__global__ void transpose_feat(const float* __restrict__ src, float* __restrict__ dst,
                               int HW, int N) {
    int total = 256 * N;
    for (int t = blockIdx.x * blockDim.x + threadIdx.x; t < total; t += gridDim.x * blockDim.x) {
        int c   = t / N;
        int rem = t % N;
        int b   = rem / HW;
        int p   = rem % HW;
        dst[t] = src[(b * 256 + c) * HW + p];
    }
}

__device__ __forceinline__ float to_tf32(float v) {
    uint32_t u;
    asm("cvt.rna.tf32.f32 %0, %1;" : "=r"(u) : "f"(v));
    return __uint_as_float(u);
}

__device__ __forceinline__ void mma_tf32(float* d, const uint32_t* a, const uint32_t* b) {
    asm volatile(
        "mma.sync.aligned.m16n8k8.row.col.f32.tf32.tf32.f32 "
        "{%0,%1,%2,%3}, {%4,%5,%6,%7}, {%8,%9}, {%0,%1,%2,%3};"
        : "+f"(d[0]), "+f"(d[1]), "+f"(d[2]), "+f"(d[3])
        : "r"(a[0]), "r"(a[1]), "r"(a[2]), "r"(a[3]), "r"(b[0]), "r"(b[1]));
}

__device__ __forceinline__ void cp_async4(uint32_t dst, const void* src, bool p) {
    int sz = p ? 4 : 0;
    asm volatile("cp.async.ca.shared.global [%0], [%1], 4, %2;\n"
                 :: "r"(dst), "l"(src), "r"(sz));
}
__device__ __forceinline__ void cp_async16(uint32_t dst, const void* src, bool p) {
    int sz = p ? 16 : 0;
    asm volatile("cp.async.cg.shared.global [%0], [%1], 16, %2;\n"
                 :: "r"(dst), "l"(src), "r"(sz));
}
__device__ __forceinline__ void cp_commit() {
    asm volatile("cp.async.commit_group;\n" ::: "memory");
}
__device__ __forceinline__ void cp_wait0() {
    asm volatile("cp.async.wait_group 0;\n" ::: "memory");
}

// conv3x3 SAME (Cin=256) as implicit GEMM over K=2304. Block tile 128x128x32.
// 8 warps (2 M x 4 N), warp tile 64x32. Raw fp32 smem (double-buffered via
// cp.async); hi/lo tf32 split at fragment read; per-k8 chunk folding.
#define BK 32
#define KT_TOTAL 72
#define SP 136
#define TILE_F (BK * SP)                 // floats per tile plane
#define SMEM_FLOATS (4 * TILE_F)         // 2 stages x (A + B)

__global__ void __launch_bounds__(256)
conv3x3_mma(const float* __restrict__ WT, const float* __restrict__ bias,
            const float* __restrict__ X, float* __restrict__ Y,
            int Cout, int N, int W, int logW, int H, int doRelu) {
    extern __shared__ float sm[];
    // layout: [stage][A|B][BK][SP]
    const int tid = threadIdx.x;
    const int n0 = blockIdx.x * 128;
    const int m0 = blockIdx.y * 128;

    const int lane = tid & 31;
    const int warp = tid >> 5;
    const int wm = warp >> 2;
    const int wn = warp & 3;
    const int g = lane >> 2;
    const int t = lane & 3;
    const int mBase = wm * 64;
    const int nBase = wn * 32;

    uint32_t smBase;
    asm("{ .reg .u64 tmp; cvta.to.shared.u64 tmp, %1; cvt.u32.u64 %0, tmp; }"
        : "=r"(smBase) : "l"(sm));

    // A loader: 4 x 16B per thread. row = (tid>>5) + 8i, f4col = tid&31
    const int aF4 = tid & 31;
    const int aRow = tid >> 5;
    const bool aOk = (m0 + aF4 * 4) < Cout;
    // B loader: 16 x 4B per thread. col = tid&127, row = (tid>>7) + 2i
    const int bCol = tid & 127;
    const int bRow = tid >> 7;
    const int nG = n0 + bCol;
    const int xc = nG & (W - 1);
    const int yc = (nG >> logW) & (H - 1);

    auto issueTile = [&](int kt, int stage) {
        uint32_t base = smBase + (uint32_t)(stage * 2 * TILE_F) * 4u;
        const float* Aq = WT + (kt * BK + aRow) * Cout + m0 + aF4 * 4;
#pragma unroll
        for (int i = 0; i < 4; i++) {
            cp_async16(base + ((aRow + 8 * i) * SP + aF4 * 4) * 4u,
                       Aq + (8 * i) * Cout, aOk);
        }
        int kpos = kt >> 3;
        int dy = kpos / 3 - 1;
        int dx = kpos - (kpos / 3) * 3 - 1;
        bool ok = ((unsigned)(xc + dx) < (unsigned)W) && ((unsigned)(yc + dy) < (unsigned)H);
        uint32_t bbase = base + (uint32_t)TILE_F * 4u;
        const float* Bq = X + ((kt & 7) * BK + bRow) * N + nG + dy * W + dx;
#pragma unroll
        for (int i = 0; i < 16; i++) {
            cp_async4(bbase + ((bRow + 2 * i) * SP + bCol) * 4u,
                      Bq + (2 * i) * N, ok);
        }
        cp_commit();
    };

    float accF[4][4][4];
#pragma unroll
    for (int mi = 0; mi < 4; mi++)
#pragma unroll
        for (int ni = 0; ni < 4; ni++)
#pragma unroll
            for (int r = 0; r < 4; r++) accF[mi][ni][r] = 0.f;

    issueTile(0, 0);

    for (int kt = 0; kt < KT_TOTAL; kt++) {
        cp_wait0();
        __syncthreads();
        if (kt + 1 < KT_TOTAL) issueTile(kt + 1, (kt + 1) & 1);

        const float* Ar = sm + (kt & 1) * 2 * TILE_F;
        const float* Br = Ar + TILE_F;

#pragma unroll
        for (int k8 = 0; k8 < 4; k8++) {
            const int kr = k8 * 8;
            uint32_t aH[4][4], aL[4][4], bH[4][2], bL[4][2];
#pragma unroll
            for (int mi = 0; mi < 4; mi++) {
                int c0 = mBase + mi * 16 + g;
#pragma unroll
                for (int s = 0; s < 4; s++) {
                    int row = kr + t + (s >> 1) * 4;       // s: 0,1 -> t; 2,3 -> t+4
                    int col = c0 + (s & 1) * 8;
                    float v = Ar[row * SP + col];
                    float h = to_tf32(v);
                    aH[mi][ (s>>1)*2 + (s&1) ] = __float_as_uint(h);
                    aL[mi][ (s>>1)*2 + (s&1) ] = __float_as_uint(to_tf32(v - h));
                }
            }
#pragma unroll
            for (int ni = 0; ni < 4; ni++) {
                int c0 = nBase + ni * 8 + g;
#pragma unroll
                for (int s = 0; s < 2; s++) {
                    float v = Br[(kr + t + 4 * s) * SP + c0];
                    float h = to_tf32(v);
                    bH[ni][s] = __float_as_uint(h);
                    bL[ni][s] = __float_as_uint(to_tf32(v - h));
                }
            }
            // NOTE: a-fragment order for m16n8k8: a0=(t,c0), a1=(t,c0+8)?? -> mapping
            // preserved from verified R3/R5 kernel: a0=(kr+t,c0), a1=(kr+t,c0+8),
            // a2=(kr+t+4,c0), a3=(kr+t+4,c0+8). Index (s>>1)*2+(s&1) reproduces it.
#pragma unroll
            for (int mi = 0; mi < 4; mi++)
#pragma unroll
                for (int ni = 0; ni < 4; ni++) {
                    float tmp[4] = {0.f, 0.f, 0.f, 0.f};
                    mma_tf32(tmp, aL[mi], bH[ni]);
                    mma_tf32(tmp, aH[mi], bL[ni]);
                    mma_tf32(tmp, aH[mi], bH[ni]);
#pragma unroll
                    for (int r = 0; r < 4; r++) accF[mi][ni][r] += tmp[r];
                }
        }
        // top-of-loop __syncthreads of next iteration protects the buffer
        // being refilled two stages ahead; no second sync needed.
    }

#pragma unroll
    for (int mi = 0; mi < 4; mi++) {
        int m_lo = m0 + mBase + mi * 16 + g;
        int m_hi = m_lo + 8;
        float bv_lo = (m_lo < Cout) ? bias[m_lo] : 0.f;
        float bv_hi = (m_hi < Cout) ? bias[m_hi] : 0.f;
#pragma unroll
        for (int ni = 0; ni < 4; ni++) {
            int n = n0 + nBase + ni * 8 + 2 * t;
            float* a4 = accF[mi][ni];
            if (m_lo < Cout) {
                float v0 = a4[0] + bv_lo, v1 = a4[1] + bv_lo;
                if (doRelu) { v0 = fmaxf(v0, 0.f); v1 = fmaxf(v1, 0.f); }
                Y[m_lo * N + n] = v0;
                Y[m_lo * N + n + 1] = v1;
            }
            if (m_hi < Cout) {
                float v2 = a4[2] + bv_hi, v3 = a4[3] + bv_hi;
                if (doRelu) { v2 = fmaxf(v2, 0.f); v3 = fmaxf(v3, 0.f); }
                Y[m_hi * N + n] = v2;
                Y[m_hi * N + n + 1] = v3;
            }
        }
    }
}

// Postprocess
__constant__ float c_scale[3] = {1.0f, 1.2599210498948732f, 1.5874010519681994f};
__constant__ float c_sqrt_ratio[3] = {0.7071067811865476f, 1.0f, 1.4142135623730951f};

__global__ void post_kernel(const float* __restrict__ cls, const float* __restrict__ reg,
                            float* __restrict__ out, int N, int HW, int W, int logW,
                            float stride, int aoff) {
    int t = blockIdx.x * blockDim.x + threadIdx.x;
    if (t >= N * NUM_ANCH) return;
    int i = t / N;
    int n = t % N;
    int b = n / HW;
    int p = n % HW;
    int x = p & (W - 1);
    int y = p >> logW;

    float best = -3.4e38f;
    int bi = 0;
#pragma unroll 4
    for (int c = 0; c < NUM_CLASSES; c++) {
        float v = cls[(i * NUM_CLASSES + c) * N + n];
        if (v > best) { best = v; bi = c; }
    }
    float score = 1.f / (1.f + expf(-best));

    float d0 = reg[(i * 4 + 0) * N + n];
    float d1 = reg[(i * 4 + 1) * N + n];
    float d2 = reg[(i * 4 + 2) * N + n];
    float d3 = reg[(i * 4 + 3) * N + n];

    float base = 4.f * stride;
    float sc = c_scale[i % 3];
    float sr = c_sqrt_ratio[i / 3];
    float wa = base * sc / sr;
    float ha = base * sc * sr;
    float cx = (x + 0.5f) * stride;
    float cy = (y + 0.5f) * stride;

    float pcx = cx + d0 * 0.1f * wa;
    float pcy = cy + d1 * 0.1f * ha;
    float pw = expf(d2 * 0.2f) * wa;
    float ph = expf(d3 * 0.2f) * ha;

    int ai = aoff + p * NUM_ANCH + i;
    int gi = b * ATOT + ai;

    out[gi] = score;
    out[BATCH * ATOT + gi] = (float)bi;
    float* bx = out + 2 * BATCH * ATOT;
    bx[(size_t)gi * 4 + 0] = pcx - 0.5f * pw;
    bx[(size_t)gi * 4 + 1] = pcy - 0.5f * ph;
    bx[(size_t)gi * 4 + 2] = pcx + 0.5f * pw;
    bx[(size_t)gi * 4 + 3] = pcy + 0.5f * ph;
}

// ============================================================================

extern "C" void kernel_launch(void* const* d_in, const int* in_sizes, int n_in,
                              void* d_out, int out_size) {
    (void)in_sizes; (void)n_in; (void)out_size;

    const float* feat[5];
    for (int i = 0; i < 5; i++) feat[i] = (const float*)d_in[i];
    const float* cls_w[5]; const float* cls_b[5];
    const float* reg_w[5]; const float* reg_b[5];
    for (int i = 0; i < 5; i++) {
        cls_w[i] = (const float*)d_in[5 + 2 * i];
        cls_b[i] = (const float*)d_in[6 + 2 * i];
        reg_w[i] = (const float*)d_in[15 + 2 * i];
        reg_b[i] = (const float*)d_in[16 + 2 * i];
    }
    float* out = (float*)d_out;

    float *px, *pa, *pb, *pcls, *preg, *pwt;
    cudaGetSymbolAddress((void**)&px, g_x);
    cudaGetSymbolAddress((void**)&pa, g_a);
    cudaGetSymbolAddress((void**)&pb, g_b);
    cudaGetSymbolAddress((void**)&pcls, g_cls);
    cudaGetSymbolAddress((void**)&preg, g_reg);
    cudaGetSymbolAddress((void**)&pwt, g_wt);

    const size_t SMEM_BYTES = SMEM_FLOATS * sizeof(float);   // 69,632
    static int attr_done = 0;
    if (!attr_done) {
        cudaFuncSetAttribute(conv3x3_mma, cudaFuncAttributeMaxDynamicSharedMemorySize,
                             (int)SMEM_BYTES);
        attr_done = 1;
    }

    const size_t CW = 9 * 256 * 256;
    const size_t OFF_CLSF = 4 * CW;
    const size_t OFF_REG0 = OFF_CLSF + (size_t)9 * 256 * 720;
    const size_t OFF_REGF = OFF_REG0 + 4 * CW;

    for (int l = 0; l < 4; l++) {
        wt_kernel<<<512, 256>>>(cls_w[l], pwt + l * CW, 256);
        wt_kernel<<<512, 256>>>(reg_w[l], pwt + OFF_REG0 + l * CW, 256);
    }
    wt_kernel<<<1024, 256>>>(cls_w[4], pwt + OFF_CLSF, 720);
    wt_kernel<<<128, 256>>>(reg_w[4], pwt + OFF_REGF, 36);

    struct Lv { int HW, W, logW; float stride; int aoff; };
    const Lv LV[5] = {
        {4096, 64, 6, 8.f, 0},
        {1024, 32, 5, 16.f, 36864},
        {256, 16, 4, 32.f, 46080},
        {64, 8, 3, 64.f, 48384},
        {16, 4, 2, 128.f, 48960},
    };

    for (int lev = 0; lev < 5; lev++) {
        const int HW = LV[lev].HW, W = LV[lev].W, logW = LV[lev].logW;
        const int N = BATCH * HW;
        const int H = W;

        {
            int total = 256 * N;
            int blocks = (total + 255) / 256;
            if (blocks > 4096) blocks = 4096;
            transpose_feat<<<blocks, 256>>>(feat[lev], px, HW, N);
        }

        dim3 g256(N / 128, 2);
        dim3 g720(N / 128, 6);
        dim3 g36(N / 128, 1);

        // cls tower
        conv3x3_mma<<<g256, 256, SMEM_BYTES>>>(pwt + 0 * CW, cls_b[0], px, pa, 256, N, W, logW, H, 1);
        conv3x3_mma<<<g256, 256, SMEM_BYTES>>>(pwt + 1 * CW, cls_b[1], pa, pb, 256, N, W, logW, H, 1);
        conv3x3_mma<<<g256, 256, SMEM_BYTES>>>(pwt + 2 * CW, cls_b[2], pb, pa, 256, N, W, logW, H, 1);
        conv3x3_mma<<<g256, 256, SMEM_BYTES>>>(pwt + 3 * CW, cls_b[3], pa, pb, 256, N, W, logW, H, 1);
        conv3x3_mma<<<g720, 256, SMEM_BYTES>>>(pwt + OFF_CLSF, cls_b[4], pb, pcls, 720, N, W, logW, H, 0);

        // reg tower
        conv3x3_mma<<<g256, 256, SMEM_BYTES>>>(pwt + OFF_REG0 + 0 * CW, reg_b[0], px, pa, 256, N, W, logW, H, 1);
        conv3x3_mma<<<g256, 256, SMEM_BYTES>>>(pwt + OFF_REG0 + 1 * CW, reg_b[1], pa, pb, 256, N, W, logW, H, 1);
        conv3x3_mma<<<g256, 256, SMEM_BYTES>>>(pwt + OFF_REG0 + 2 * CW, reg_b[2], pb, pa, 256, N, W, logW, H, 1);
        conv3x3_mma<<<g256, 256, SMEM_BYTES>>>(pwt + OFF_REG0 + 3 * CW, reg_b[3], pa, pb, 256, N, W, logW, H, 1);
        conv3x3_mma<<<g36, 256, SMEM_BYTES>>>(pwt + OFF_REGF, reg_b[4], pb, preg, 36, N, W, logW, H, 0);

        {
            int total = N * NUM_ANCH;
            int blocks = (total + 255) / 256;
            post_kernel<<<blocks, 256>>>(pcls, preg, out, N, HW, W, logW,
                                         LV[lev].stride, LV[lev].aoff);
        }
    }
}